// round 8
// baseline (speedup 1.0000x reference)
#include <cuda_runtime.h>
#include <cuda_bf16.h>

#define DEVFN static __device__ __forceinline__

namespace {
constexpr int L_ = 512, NB = 64, IND = 256, HD = 1024;
constexpr unsigned NH = (unsigned)NB * HD;                        // 65536
constexpr unsigned ALLC_OFF = (unsigned)L_ * NH;                  // 33554432
constexpr unsigned HN_OFF = ALLC_OFF + (unsigned)L_ * 2u * NH;    // 100663296
constexpr unsigned CN_OFF = HN_OFF + 2u * NH;
}

// Persistent scratch (static __device__ allocation — sanctioned pattern).
__device__ __align__(16) unsigned g_Wp0[64 * 80 * 1024];    // layer0 packed bf16-split weights (21 MB)
__device__ __align__(16) unsigned g_Wp1[64 * 128 * 1024];   // layer1 (33.5 MB)
__device__ __align__(16) float g_h0buf[2][NH];              // double-buffered h, layer0
__device__ __align__(16) float g_h1buf[2][NH];              // double-buffered h, layer1
__device__ unsigned g_bar;                                  // grid barrier (monotonic)

// Split fp32 pair into packed bf16x2 hi and lo planes.
DEVFN void split2(float x0, float x1, unsigned& hi, unsigned& lo) {
    __nv_bfloat16 h0 = __float2bfloat16(x0), h1 = __float2bfloat16(x1);
    float r0 = x0 - __bfloat162float(h0), r1 = x1 - __bfloat162float(h1);
    __nv_bfloat16 l0 = __float2bfloat16(r0), l1 = __float2bfloat16(r1);
    hi = (unsigned)__bfloat16_as_ushort(h0) | ((unsigned)__bfloat16_as_ushort(h1) << 16);
    lo = (unsigned)__bfloat16_as_ushort(l0) | ((unsigned)__bfloat16_as_ushort(l1) << 16);
}

DEVFN void mma16816(float* c, const unsigned* a, unsigned b0, unsigned b1) {
    asm volatile(
        "mma.sync.aligned.m16n8k16.row.col.f32.bf16.bf16.f32 "
        "{%0,%1,%2,%3}, {%4,%5,%6,%7}, {%8,%9}, {%0,%1,%2,%3};\n"
        : "+f"(c[0]), "+f"(c[1]), "+f"(c[2]), "+f"(c[3])
        : "r"(a[0]), "r"(a[1]), "r"(a[2]), "r"(a[3]), "r"(b0), "r"(b1));
}

DEVFN void cp16(void* sdst, const void* gsrc) {
    unsigned s = (unsigned)__cvta_generic_to_shared(sdst);
    asm volatile("cp.async.cg.shared.global [%0], [%1], 16;\n" :: "r"(s), "l"(gsrc));
}
DEVFN void cp_commit() { asm volatile("cp.async.commit_group;\n"); }
template <int N> DEVFN void cp_wait() { asm volatile("cp.async.wait_group %0;\n" :: "n"(N)); }

DEVFN float sigf(float x) { return 1.f / (1.f + __expf(-x)); }
DEVFN float tanhf_(float x) {
    float a = fabsf(x);
    float e = __expf(-2.f * a);
    float r = (1.f - e) / (1.f + e);
    return copysignf(r, x);
}

// ---------------------------------------------------------------------------
// Reset barrier + place initial h states into the correct parity slots.
// layer0 reads slot 1 at epoch 0; layer1 reads slot 0 at epoch 1.
// ---------------------------------------------------------------------------
__global__ void init_kernel(const float* __restrict__ h0) {
    unsigned i = blockIdx.x * blockDim.x + threadIdx.x;
    if (i == 0) g_bar = 0u;
    for (; i < 2u * NH; i += gridDim.x * blockDim.x) {
        if (i < NH) g_h0buf[1][i] = h0[i];
        else        g_h1buf[0][i - NH] = h0[i];
    }
}

// ---------------------------------------------------------------------------
// Pack weights into mma-B-fragment-exact, gate-interleaved, bf16-split layout.
// Element u32 at ((c*S16+s)*8+blk)*2+plane)*64 + lane*2 + bsel packs bf16x2 of
// W[row][k0], W[row][k0+1] with k0 = s*16 + (lane&3)*2 + bsel*8,
// col = blk*8 + (lane>>2), gate = col>>4, cell = c*16 + (col&15),
// row = gate*H + cell;  k < Din -> w_ih, else w_hh (K = [input ; hidden]).
// ---------------------------------------------------------------------------
__global__ void permute_kernel(
    const float* __restrict__ wih0, const float* __restrict__ whh0,
    const float* __restrict__ wih1, const float* __restrict__ whh1)
{
    const int tot0 = 64 * 80 * 1024;
    const int tot1 = 64 * 128 * 1024;
    for (int idx = blockIdx.x * blockDim.x + threadIdx.x; idx < tot0 + tot1;
         idx += gridDim.x * blockDim.x) {
        const int layer = idx >= tot0 ? 1 : 0;
        const int li = layer ? idx - tot0 : idx;
        const int S16 = layer ? 128 : 80;
        const int Din = layer ? HD : IND;
        const float* wih = layer ? wih1 : wih0;
        const float* whh = layer ? whh1 : whh0;
        const int per_c = S16 * 1024;
        const int c = li / per_c;
        const int rem = li - c * per_c;
        const int s = rem >> 10;
        const int r2 = rem & 1023;
        const int blk = r2 >> 7;
        const int r3 = r2 & 127;
        const int plane = r3 >> 6;
        const int r4 = r3 & 63;
        const int lane = r4 >> 1, bsel = r4 & 1;
        const int k0 = s * 16 + (lane & 3) * 2 + bsel * 8;
        const int col = blk * 8 + (lane >> 2);
        const int row = (col >> 4) * HD + c * 16 + (col & 15);
        float v0, v1;
        if (k0 < Din) { v0 = wih[row * Din + k0]; v1 = wih[row * Din + k0 + 1]; }
        else          { v0 = whh[row * HD + k0 - Din]; v1 = whh[row * HD + k0 + 1 - Din]; }
        unsigned hi, lo;
        split2(v0, v1, hi, lo);
        const unsigned val = plane ? lo : hi;
        if (layer) g_Wp1[li] = val;
        else       g_Wp0[li] = val;
    }
}

// ---------------------------------------------------------------------------
// Persistent LSTM. 128 CTAs x 128 threads. CTA = (layer = bid>>6, cblk = bid&63).
// Per epoch: gates = [x_or_h0 ; h_prev] @ Wp^T + (b_ih+b_hh), fused pointwise.
// Warp w owns batch rows [16w,16w+16); CTA owns 64 gate-cols (gate-major).
// ---------------------------------------------------------------------------
__global__ void __launch_bounds__(128, 1) lstm_kernel(
    const float* __restrict__ x, const float* __restrict__ c0,
    const float* __restrict__ bih0, const float* __restrict__ bhh0,
    const float* __restrict__ bih1, const float* __restrict__ bhh1,
    float* __restrict__ out)
{
    __shared__ float As[2][64 * 40];     // 64 rows x (32 K + 8 pad), double-buffered
    __shared__ unsigned Bs[2][2048];     // 2 k16-steps x 8 blk x 2 planes x 64

    const int layer = blockIdx.x >> 6;
    const int cblk = blockIdx.x & 63;
    const int w = threadIdx.x >> 5, lane = threadIdx.x & 31;
    const int g = lane >> 2, t = lane & 3;
    const int Din = layer ? HD : IND;
    const int S16 = layer ? 128 : 80;
    const int nch = layer ? 64 : 40;     // 32-wide K chunks
    const unsigned* __restrict__ Wp = layer ? g_Wp1 : g_Wp0;
    const float* bih = layer ? bih1 : bih0;
    const float* bhh = layer ? bhh1 : bhh0;

    // Per-thread fused biases: blk -> gate = blk>>1, cell-half p = blk&1.
    float2 bias[8];
#pragma unroll
    for (int blk = 0; blk < 8; blk++) {
        const int r = (blk >> 1) * HD + cblk * 16 + (blk & 1) * 8 + t * 2;
        bias[blk].x = bih[r] + bhh[r];
        bias[blk].y = bih[r + 1] + bhh[r + 1];
    }
    // Cell state lives in registers for all 512 steps: [rho][p*2+q].
    float cst[8];
#pragma unroll
    for (int rho = 0; rho < 2; rho++)
#pragma unroll
        for (int p = 0; p < 2; p++)
#pragma unroll
            for (int q = 0; q < 2; q++) {
                const int n = 16 * w + g + 8 * rho;
                const int cell = cblk * 16 + p * 8 + t * 2 + q;
                cst[rho * 4 + p * 2 + q] = c0[(unsigned)layer * NH + (unsigned)n * HD + cell];
            }

    for (int e = 0; e <= 512; e++) {
        const int tstep = layer ? e - 1 : e;
        const bool active = layer ? (e >= 1) : (e < 512);
        const int rs = 1 - (e & 1), ws = e & 1;
        if (active) {
            const float* s0p; int s0st;
            if (layer == 0) { s0p = x + (unsigned)tstep * NB * IND; s0st = IND; }
            else            { s0p = g_h0buf[rs]; s0st = HD; }
            const float* s1p = layer ? g_h1buf[rs] : g_h0buf[rs];

            float acc[8][4];
#pragma unroll
            for (int blk = 0; blk < 8; blk++) {
                acc[blk][0] = acc[blk][2] = bias[blk].x;
                acc[blk][1] = acc[blk][3] = bias[blk].y;
            }

            auto load_chunk = [&](int ch) {
                const int kb = ch * 32;
                const float* sA = (kb < Din) ? (s0p + kb) : (s1p + (kb - Din));
                const int st = (kb < Din) ? s0st : HD;
                float* ad = As[ch & 1];
                unsigned* bd = Bs[ch & 1];
                const unsigned* bsrc = Wp + ((unsigned)cblk * S16 + ch * 2) * 1024u;
#pragma unroll
                for (int i = 0; i < 4; i++) {
                    const int idx = threadIdx.x + i * 128;
                    const int row = idx >> 3, seg = idx & 7;
                    cp16(ad + row * 40 + seg * 4, sA + (unsigned)row * st + seg * 4);
                    cp16(bd + idx * 4, bsrc + idx * 4);
                }
                cp_commit();
            };

            load_chunk(0);
            for (int ch = 0; ch < nch; ch++) {
                if (ch + 1 < nch) { load_chunk(ch + 1); cp_wait<1>(); }
                else cp_wait<0>();
                __syncthreads();
                const int buf = ch & 1;
#pragma unroll
                for (int sl = 0; sl < 2; sl++) {
                    const float* ab = &As[buf][(16 * w + g) * 40 + sl * 16 + 2 * t];
                    const float2 v00 = *(const float2*)ab;
                    const float2 v01 = *(const float2*)(ab + 8);
                    const float2 v10 = *(const float2*)(ab + 8 * 40);
                    const float2 v11 = *(const float2*)(ab + 8 * 40 + 8);
                    unsigned ahi[4], alo[4];
                    split2(v00.x, v00.y, ahi[0], alo[0]);
                    split2(v10.x, v10.y, ahi[1], alo[1]);
                    split2(v01.x, v01.y, ahi[2], alo[2]);
                    split2(v11.x, v11.y, ahi[3], alo[3]);
#pragma unroll
                    for (int blk = 0; blk < 8; blk++) {
                        const unsigned* bb = &Bs[buf][(sl * 8 + blk) * 128 + lane * 2];
                        const uint2 bh = *(const uint2*)bb;
                        const uint2 bl = *(const uint2*)(bb + 64);
                        mma16816(acc[blk], ahi, bh.x, bh.y);   // hi*hi
                        mma16816(acc[blk], ahi, bl.x, bl.y);   // hi*lo
                        mma16816(acc[blk], alo, bh.x, bh.y);   // lo*hi
                    }
                }
                __syncthreads();
            }

            // Fused LSTM pointwise epilogue: thread holds i,f,g,o for its cells.
            float* hw = layer ? g_h1buf[ws] : g_h0buf[ws];
#pragma unroll
            for (int rho = 0; rho < 2; rho++) {
                const int n = 16 * w + g + 8 * rho;
#pragma unroll
                for (int p = 0; p < 2; p++) {
                    const int cell = cblk * 16 + p * 8 + t * 2;
                    float2 h2, c2;
#pragma unroll
                    for (int q = 0; q < 2; q++) {
                        const int idx = rho * 2 + q;
                        const float ii = sigf(acc[0 + p][idx]);
                        const float ff = sigf(acc[2 + p][idx]);
                        const float gg = tanhf_(acc[4 + p][idx]);
                        const float oo = sigf(acc[6 + p][idx]);
                        const int cs = rho * 4 + p * 2 + q;
                        const float cc = ff * cst[cs] + ii * gg;
                        cst[cs] = cc;
                        const float hh = oo * tanhf_(cc);
                        if (q) { h2.y = hh; c2.y = cc; } else { h2.x = hh; c2.x = cc; }
                    }
                    *(float2*)&hw[(unsigned)n * HD + cell] = h2;
                    *(float2*)&out[ALLC_OFF + ((unsigned)(tstep * 2 + layer) * NB + n) * HD + cell] = c2;
                    if (layer)
                        *(float2*)&out[((unsigned)tstep * NB + n) * HD + cell] = h2;
                    if (tstep == 511) {
                        *(float2*)&out[HN_OFF + ((unsigned)layer * NB + n) * HD + cell] = h2;
                        *(float2*)&out[CN_OFF + ((unsigned)layer * NB + n) * HD + cell] = c2;
                    }
                }
            }
        }
        if (e < 512) {   // grid barrier (no barrier after final epoch; init resets g_bar)
            __threadfence();
            __syncthreads();
            if (threadIdx.x == 0) {
                atomicAdd(&g_bar, 1u);
                const unsigned target = (unsigned)(e + 1) * 128u;
                unsigned v;
                while (true) {
                    asm volatile("ld.acquire.gpu.u32 %0, [%1];" : "=r"(v) : "l"(&g_bar));
                    if (v >= target) break;
                    __nanosleep(32);
                }
            }
            __syncthreads();
        }
    }
}

extern "C" void kernel_launch(void* const* d_in, const int* in_sizes, int n_in,
                              void* d_out, int out_size) {
    (void)in_sizes; (void)n_in; (void)out_size;
    const float* x    = (const float*)d_in[0];
    const float* h0   = (const float*)d_in[1];
    const float* c0   = (const float*)d_in[2];
    const float* wih0 = (const float*)d_in[3];
    const float* whh0 = (const float*)d_in[4];
    const float* bih0 = (const float*)d_in[5];
    const float* bhh0 = (const float*)d_in[6];
    const float* wih1 = (const float*)d_in[7];
    const float* whh1 = (const float*)d_in[8];
    const float* bih1 = (const float*)d_in[9];
    const float* bhh1 = (const float*)d_in[10];
    float* out = (float*)d_out;

    init_kernel<<<64, 256>>>(h0);
    permute_kernel<<<4096, 256>>>(wih0, whh0, wih1, whh1);
    lstm_kernel<<<128, 128>>>(x, c0, bih0, bhh0, bih1, bhh1, out);
}